// round 9
// baseline (speedup 1.0000x reference)
#include <cuda_runtime.h>
#include <math.h>

// ---------------------------------------------------------------------------
// YOLO loss (3 layers, B=16, na=3, C=85, H/W = 80/40/20, nc=80)  — ONE kernel.
//
// lobj = mean(softplus(x)) - mean(x*t), second term sparse (<=2700 cells).
// Dense pass streams only pred channel 4. Row warps compute CIoU/lcls and
// scatter winners into g_tobj via packed atomicMax. The LAST block (atomic
// counter + threadfence) resolves winners, applies the sparse correction,
// writes the output, and resets all scratch state (replay invariant).
// ---------------------------------------------------------------------------

#define B_IMG   16
#define NA      3
#define NCLS    80
#define CDIM    85

#define N0 307200
#define N1 76800
#define N2 19200
#define NTOT (N0 + N1 + N2)       // 403200
#define STREAM_BLOCKS 525         // 403200 / (256 threads * 3 cells)
#define MAX_ROWS 4096

__device__ unsigned long long g_tobj[NTOT];
__device__ int   g_rcell[MAX_ROWS];
__device__ float g_rx[MAX_ROWS];
__device__ float g_rt[MAX_ROWS];
// [l*3+0]=sum(1-iou), [l*3+1]=nvalid, [l*3+2]=sum lcls (l=0..2), [9]=softplus
__device__ float g_acc[10];
__device__ unsigned int g_count;

__device__ __forceinline__ float bce_logits(float x, float t) {
    return fmaxf(x, 0.0f) - x * t + log1pf(expf(-fabsf(x)));
}

__global__ __launch_bounds__(256)
void yolo_kernel(const float* __restrict__ p0,
                 const float* __restrict__ p1,
                 const float* __restrict__ p2,
                 const float* __restrict__ targets,
                 const float* __restrict__ anchors,
                 float* __restrict__ out,
                 int out_size,
                 int nt)
{
    const int rows_per_layer = NA * nt;
    const int total_rows = 3 * rows_per_layer;

    if (blockIdx.x < STREAM_BLOCKS) {
        // ---- dense objectness stream: 3 cells/thread, weighted softplus ----
        const int g0 = blockIdx.x * 768 + threadIdx.x;
        float x[3], wt[3];
        #pragma unroll
        for (int i = 0; i < 3; i++) {
            const int g = g0 + i * 256;
            const float* ptr;
            if (g < N0)           { ptr = p0 + (size_t)g * CDIM + 4;              wt[i] = 1.0f / (float)N0; }
            else if (g < N0 + N1) { ptr = p1 + (size_t)(g - N0) * CDIM + 4;       wt[i] = 1.0f / (float)N1; }
            else                  { ptr = p2 + (size_t)(g - N0 - N1) * CDIM + 4;  wt[i] = 1.0f / (float)N2; }
            x[i] = __ldcs(ptr);
        }
        float acc = 0.0f;
        #pragma unroll
        for (int i = 0; i < 3; i++) {
            const float sp = fmaxf(x[i], 0.0f) +
                             __logf(1.0f + __expf(-fabsf(x[i])));
            acc += sp * wt[i];
        }
        __shared__ float s[8];
        const int lane = threadIdx.x & 31;
        const int wrp  = threadIdx.x >> 5;
        #pragma unroll
        for (int o = 16; o; o >>= 1)
            acc += __shfl_down_sync(0xffffffffu, acc, o);
        if (lane == 0) s[wrp] = acc;
        __syncthreads();
        if (threadIdx.x < 8) {
            float w = s[threadIdx.x];
            #pragma unroll
            for (int o = 4; o; o >>= 1)
                w += __shfl_down_sync(0x000000ffu, w, o);
            if (threadIdx.x == 0)
                atomicAdd(&g_acc[9], w);
        }
    } else {
        // ---- row path: one warp per (layer, anchor, target) ----
        const int warp = (blockIdx.x - STREAM_BLOCKS) * 8 + (threadIdx.x >> 5);
        const int lane = threadIdx.x & 31;

        if (warp < total_rows) {
            const int li = warp / rows_per_layer;
            const int r  = warp - li * rows_per_layer;    // a*nt + ti
            const int a  = r / nt;
            const int ti = r - a * nt;

            const int Wd = (li == 0) ? 80 : (li == 1) ? 40 : 20;
            const int Hd = Wd;
            const float* p = (li == 0) ? p0 : (li == 1) ? p1 : p2;
            const int base = (li == 0) ? 0 : (li == 1) ? N0 : (N0 + N1);

            const float timg = targets[ti * 6 + 0];
            const float tcls = targets[ti * 6 + 1];
            const float gx = targets[ti * 6 + 2] * (float)Wd;
            const float gy = targets[ti * 6 + 3] * (float)Hd;
            const float gw = targets[ti * 6 + 4] * (float)Wd;
            const float gh = targets[ti * 6 + 5] * (float)Hd;

            const float aw = anchors[(li * 3 + a) * 2 + 0];
            const float ah = anchors[(li * 3 + a) * 2 + 1];
            const float rw = gw / aw, rh = gh / ah;
            const float mr = fmaxf(fmaxf(rw, 1.0f / rw), fmaxf(rh, 1.0f / rh));

            if (!(mr < 4.0f)) {
                if (lane == 0) g_rcell[warp] = -1;
            } else {
                const int b = (int)timg;
                const int c = (int)tcls;
                const int gij_x = (int)gx;
                const int gij_y = (int)gy;
                const int gi = min(max(gij_x, 0), Wd - 1);
                const int gj = min(max(gij_y, 0), Hd - 1);
                const int match = B_IMG - 1 - b;

                const int cell = ((match * NA + a) * Hd + gj) * Wd + gi;
                const float* ps = p + (size_t)cell * CDIM;

                const float v0 = ps[lane];
                const float v1 = ps[lane + 32];
                const float v2 = (lane + 64 < CDIM) ? ps[lane + 64] : 0.0f;

                float lc = 0.0f;
                if (lane >= 5)
                    lc += bce_logits(v0, (lane - 5) == c ? 1.0f : 0.0f);
                lc += bce_logits(v1, (lane + 32 - 5) == c ? 1.0f : 0.0f);
                if (lane + 64 < CDIM)
                    lc += bce_logits(v2, (lane + 64 - 5) == c ? 1.0f : 0.0f);
                #pragma unroll
                for (int o = 16; o; o >>= 1)
                    lc += __shfl_down_sync(0xffffffffu, lc, o);

                const float ps0 = __shfl_sync(0xffffffffu, v0, 0);
                const float ps1 = __shfl_sync(0xffffffffu, v0, 1);
                const float ps2 = __shfl_sync(0xffffffffu, v0, 2);
                const float ps3 = __shfl_sync(0xffffffffu, v0, 3);
                const float ps4 = __shfl_sync(0xffffffffu, v0, 4);

                if (lane == 0) {
                    // reference quirk: anch = anchors[a, a]
                    const float anw = anchors[(a * 3 + a) * 2 + 0];
                    const float anh = anchors[(a * 3 + a) * 2 + 1];

                    const float px = 1.0f / (1.0f + expf(-ps0));
                    const float py = 1.0f / (1.0f + expf(-ps1));
                    const float pw = expf(ps2) * anw;
                    const float ph = expf(ps3) * anh;
                    const float tx = gx - (float)gij_x;
                    const float ty = gy - (float)gij_y;

                    const float eps = 1e-9f;
                    const float b1x1 = px - pw * 0.5f, b1x2 = px + pw * 0.5f;
                    const float b1y1 = py - ph * 0.5f, b1y2 = py + ph * 0.5f;
                    const float b2x1 = tx - gw * 0.5f, b2x2 = tx + gw * 0.5f;
                    const float b2y1 = ty - gh * 0.5f, b2y2 = ty + gh * 0.5f;
                    const float inter =
                        fmaxf(fminf(b1x2, b2x2) - fmaxf(b1x1, b2x1), 0.0f) *
                        fmaxf(fminf(b1y2, b2y2) - fmaxf(b1y1, b2y1), 0.0f);
                    const float w1 = b1x2 - b1x1, h1 = b1y2 - b1y1 + eps;
                    const float w2 = b2x2 - b2x1, h2 = b2y2 - b2y1 + eps;
                    const float uni = w1 * h1 + w2 * h2 - inter + eps;
                    const float iou0 = inter / uni;
                    const float cw = fmaxf(b1x2, b2x2) - fminf(b1x1, b2x1);
                    const float chh = fmaxf(b1y2, b2y2) - fminf(b1y1, b2y1);
                    const float c2 = cw * cw + chh * chh + eps;
                    const float dx = b2x1 + b2x2 - b1x1 - b1x2;
                    const float dy = b2y1 + b2y2 - b1y1 - b1y2;
                    const float rho2 = (dx * dx + dy * dy) * 0.25f;
                    const float dat = atanf(w2 / h2) - atanf(w1 / h1);
                    const float v = 0.4052847345693511f * dat * dat;
                    const float alpha = v / (1.0f + eps - iou0 + v);
                    const float iou = iou0 - (rho2 / c2 + v * alpha);

                    atomicAdd(&g_acc[li * 3 + 0], 1.0f - iou);
                    atomicAdd(&g_acc[li * 3 + 1], 1.0f);
                    atomicAdd(&g_acc[li * 3 + 2], lc);

                    const float tval = fmaxf(iou, 0.0f);
                    const unsigned long long packed =
                        (((unsigned long long)(r + 1)) << 32) |
                        (unsigned long long)__float_as_uint(tval);
                    atomicMax(&g_tobj[base + cell], packed);

                    g_rcell[warp] = base + cell;
                    g_rx[warp] = ps4;
                    g_rt[warp] = tval;
                }
            }
        }
    }

    // ------------- last-block finalize -------------
    __shared__ bool is_last;
    if (threadIdx.x == 0) {
        __threadfence();
        unsigned int done = atomicAdd(&g_count, 1u);
        is_last = (done == gridDim.x - 1);
    }
    __syncthreads();
    if (!is_last) return;

    const float wly[3] = {1.0f / (float)N0, 1.0f / (float)N1, 1.0f / (float)N2};
    float corr = 0.0f;
    for (int j = threadIdx.x; j < total_rows; j += 256) {
        const int cell = g_rcell[j];
        if (cell >= 0) {
            const int li = j / rows_per_layer;
            const int r  = j - li * rows_per_layer;
            const float tval = g_rt[j];
            const unsigned long long packed =
                (((unsigned long long)(r + 1)) << 32) |
                (unsigned long long)__float_as_uint(tval);
            if (g_tobj[cell] == packed) {          // this row won the cell
                corr += g_rx[j] * tval * wly[li];
                g_tobj[cell] = 0ull;               // restore zero invariant
            }
        }
    }

    __shared__ float sf[8];
    const int lane = threadIdx.x & 31;
    const int wrp  = threadIdx.x >> 5;
    #pragma unroll
    for (int o = 16; o; o >>= 1)
        corr += __shfl_down_sync(0xffffffffu, corr, o);
    if (lane == 0) sf[wrp] = corr;
    __syncthreads();
    if (threadIdx.x == 0) {
        float w = 0.0f;
        #pragma unroll
        for (int i = 0; i < 8; i++) w += sf[i];

        volatile float* va = g_acc;
        float lbox = 0.0f, lcls = 0.0f;
        #pragma unroll
        for (int l = 0; l < 3; l++) {
            const float nv = fmaxf(va[l * 3 + 1], 1.0f);
            lbox += va[l * 3 + 0] / nv;
            lcls += va[l * 3 + 2] / (nv * (float)NCLS);
        }
        const float lobj = va[9] - w;              // dense softplus - x*t corr
        lbox *= 0.05f;
        lcls *= 0.5f;
        const float loss = lbox + lobj + lcls;

        if (out_size >= 5) {
            out[0] = loss;
            out[1] = lbox;
            out[2] = lobj;
            out[3] = lcls;
            out[4] = loss;
            for (int i = 5; i < out_size; i++) out[i] = 0.0f;
        } else if (out_size == 4) {
            out[0] = lbox; out[1] = lobj; out[2] = lcls; out[3] = loss;
        } else {
            for (int i = 0; i < out_size; i++) out[i] = loss;
        }

        #pragma unroll
        for (int i = 0; i < 10; i++) g_acc[i] = 0.0f;
        g_count = 0u;
    }
}

extern "C" void kernel_launch(void* const* d_in, const int* in_sizes, int n_in,
                              void* d_out, int out_size)
{
    const float* p0 = (const float*)d_in[0];
    const float* p1 = (const float*)d_in[1];
    const float* p2 = (const float*)d_in[2];
    const float* tg = (const float*)d_in[3];
    const float* an = (const float*)d_in[4];

    int nt = in_sizes[3] / 6;                        // 300
    int total_rows = 3 * NA * nt;                    // 2700
    int row_blocks = (total_rows * 32 + 255) / 256;  // 338

    yolo_kernel<<<STREAM_BLOCKS + row_blocks, 256>>>(
        p0, p1, p2, tg, an, (float*)d_out, out_size, nt);
}

// round 10
// speedup vs baseline: 1.3283x; 1.3283x over previous
#include <cuda_runtime.h>
#include <math.h>

// ---------------------------------------------------------------------------
// YOLO loss (3 layers, B=16, na=3, C=85, H/W = 80/40/20, nc=80)
//
// lobj = mean(softplus(x)) - mean(x * t_winner).  The sparse term is built
// incrementally via the telescoping atomicMax trick: when a row improves a
// cell's packed (priority, t) entry, it adds x*(t_new - t_displaced), so the
// per-cell sum converges to x*t_winner under ANY serialization order.
// No winner-resolution read pass is needed.
//
// Kernel 1: dense softplus stream (7 cells/thread, MLP=7) + row warps.
// Kernel 2: blind-clear touched g_tobj cells + tiny scalar epilogue.
//
// Scratch (__device__ globals, zero at load; invariant restored each replay):
//   g_tobj  : packed entries at matched cells only (cleared by kernel 2)
//   g_rcell : per-row touched cell index or -1 (rewritten every replay)
//   g_acc   : [l*3+0]=sum(1-iou) [l*3+1]=nvalid [l*3+2]=sum lcls (l=0..2)
//             [9] = lobj accumulator (softplus stream - x*t corrections)
// ---------------------------------------------------------------------------

#define B_IMG   16
#define NA      3
#define NCLS    80
#define CDIM    85

#define N0 307200
#define N1 76800
#define N2 19200
#define NTOT (N0 + N1 + N2)       // 403200
#define CELLS_PER_THREAD 7
#define STREAM_BLOCKS 225         // 403200 / (256 * 7)
#define MAX_ROWS 4096

__device__ unsigned long long g_tobj[NTOT];
__device__ int   g_rcell[MAX_ROWS];
__device__ float g_acc[10];

__device__ __forceinline__ float bce_logits(float x, float t) {
    return fmaxf(x, 0.0f) - x * t + log1pf(expf(-fabsf(x)));
}

// ---------------------------------------------------------------------------
// Kernel 1: dense stream + row warps
// ---------------------------------------------------------------------------
__global__ __launch_bounds__(256)
void main_kernel(const float* __restrict__ p0,
                 const float* __restrict__ p1,
                 const float* __restrict__ p2,
                 const float* __restrict__ targets,
                 const float* __restrict__ anchors,
                 int nt)
{
    const int rows_per_layer = NA * nt;
    const int total_rows = 3 * rows_per_layer;

    if (blockIdx.x < STREAM_BLOCKS) {
        // ---- dense objectness: 7 independent strided loads per thread ----
        const int g0 = blockIdx.x * (256 * CELLS_PER_THREAD) + threadIdx.x;
        float x[CELLS_PER_THREAD], wt[CELLS_PER_THREAD];
        #pragma unroll
        for (int i = 0; i < CELLS_PER_THREAD; i++) {
            const int g = g0 + i * 256;
            const float* ptr;
            if (g < N0)           { ptr = p0 + (size_t)g * CDIM + 4;              wt[i] = 1.0f / (float)N0; }
            else if (g < N0 + N1) { ptr = p1 + (size_t)(g - N0) * CDIM + 4;       wt[i] = 1.0f / (float)N1; }
            else                  { ptr = p2 + (size_t)(g - N0 - N1) * CDIM + 4;  wt[i] = 1.0f / (float)N2; }
            x[i] = __ldcs(ptr);
        }
        float acc = 0.0f;
        #pragma unroll
        for (int i = 0; i < CELLS_PER_THREAD; i++) {
            const float sp = fmaxf(x[i], 0.0f) +
                             __logf(1.0f + __expf(-fabsf(x[i])));
            acc += sp * wt[i];
        }
        __shared__ float s[8];
        const int lane = threadIdx.x & 31;
        const int wrp  = threadIdx.x >> 5;
        #pragma unroll
        for (int o = 16; o; o >>= 1)
            acc += __shfl_down_sync(0xffffffffu, acc, o);
        if (lane == 0) s[wrp] = acc;
        __syncthreads();
        if (threadIdx.x < 8) {
            float w = s[threadIdx.x];
            #pragma unroll
            for (int o = 4; o; o >>= 1)
                w += __shfl_down_sync(0x000000ffu, w, o);
            if (threadIdx.x == 0)
                atomicAdd(&g_acc[9], w);
        }
        return;
    }

    // ---- row path: one warp per (layer, anchor, target) ----
    const int warp = (blockIdx.x - STREAM_BLOCKS) * 8 + (threadIdx.x >> 5);
    const int lane = threadIdx.x & 31;
    if (warp >= total_rows) return;

    const int li = warp / rows_per_layer;
    const int r  = warp - li * rows_per_layer;    // a*nt + ti
    const int a  = r / nt;
    const int ti = r - a * nt;

    const int Wd = (li == 0) ? 80 : (li == 1) ? 40 : 20;
    const int Hd = Wd;
    const float* p = (li == 0) ? p0 : (li == 1) ? p1 : p2;
    const int base = (li == 0) ? 0 : (li == 1) ? N0 : (N0 + N1);
    const float wly = (li == 0) ? (1.0f / (float)N0)
                   : (li == 1) ? (1.0f / (float)N1) : (1.0f / (float)N2);

    const float timg = targets[ti * 6 + 0];
    const float tcls = targets[ti * 6 + 1];
    const float gx = targets[ti * 6 + 2] * (float)Wd;
    const float gy = targets[ti * 6 + 3] * (float)Hd;
    const float gw = targets[ti * 6 + 4] * (float)Wd;
    const float gh = targets[ti * 6 + 5] * (float)Hd;

    const float aw = anchors[(li * 3 + a) * 2 + 0];
    const float ah = anchors[(li * 3 + a) * 2 + 1];
    const float rw = gw / aw, rh = gh / ah;
    const float mr = fmaxf(fmaxf(rw, 1.0f / rw), fmaxf(rh, 1.0f / rh));
    if (!(mr < 4.0f)) {
        if (lane == 0) g_rcell[warp] = -1;
        return;
    }

    const int b = (int)timg;
    const int c = (int)tcls;
    const int gij_x = (int)gx;
    const int gij_y = (int)gy;
    const int gi = min(max(gij_x, 0), Wd - 1);
    const int gj = min(max(gij_y, 0), Hd - 1);
    const int match = B_IMG - 1 - b;

    const int cell = ((match * NA + a) * Hd + gj) * Wd + gi;
    const float* ps = p + (size_t)cell * CDIM;

    const float v0 = ps[lane];
    const float v1 = ps[lane + 32];
    const float v2 = (lane + 64 < CDIM) ? ps[lane + 64] : 0.0f;

    float lc = 0.0f;
    if (lane >= 5)
        lc += bce_logits(v0, (lane - 5) == c ? 1.0f : 0.0f);
    lc += bce_logits(v1, (lane + 32 - 5) == c ? 1.0f : 0.0f);
    if (lane + 64 < CDIM)
        lc += bce_logits(v2, (lane + 64 - 5) == c ? 1.0f : 0.0f);
    #pragma unroll
    for (int o = 16; o; o >>= 1)
        lc += __shfl_down_sync(0xffffffffu, lc, o);

    const float ps0 = __shfl_sync(0xffffffffu, v0, 0);
    const float ps1 = __shfl_sync(0xffffffffu, v0, 1);
    const float ps2 = __shfl_sync(0xffffffffu, v0, 2);
    const float ps3 = __shfl_sync(0xffffffffu, v0, 3);
    const float ps4 = __shfl_sync(0xffffffffu, v0, 4);

    if (lane == 0) {
        // reference quirk: anch = anchors[a, a]
        const float anw = anchors[(a * 3 + a) * 2 + 0];
        const float anh = anchors[(a * 3 + a) * 2 + 1];

        const float px = 1.0f / (1.0f + expf(-ps0));
        const float py = 1.0f / (1.0f + expf(-ps1));
        const float pw = expf(ps2) * anw;
        const float ph = expf(ps3) * anh;
        const float tx = gx - (float)gij_x;
        const float ty = gy - (float)gij_y;

        const float eps = 1e-9f;
        const float b1x1 = px - pw * 0.5f, b1x2 = px + pw * 0.5f;
        const float b1y1 = py - ph * 0.5f, b1y2 = py + ph * 0.5f;
        const float b2x1 = tx - gw * 0.5f, b2x2 = tx + gw * 0.5f;
        const float b2y1 = ty - gh * 0.5f, b2y2 = ty + gh * 0.5f;
        const float inter =
            fmaxf(fminf(b1x2, b2x2) - fmaxf(b1x1, b2x1), 0.0f) *
            fmaxf(fminf(b1y2, b2y2) - fmaxf(b1y1, b2y1), 0.0f);
        const float w1 = b1x2 - b1x1, h1 = b1y2 - b1y1 + eps;
        const float w2 = b2x2 - b2x1, h2 = b2y2 - b2y1 + eps;
        const float uni = w1 * h1 + w2 * h2 - inter + eps;
        const float iou0 = inter / uni;
        const float cw = fmaxf(b1x2, b2x2) - fminf(b1x1, b2x1);
        const float chh = fmaxf(b1y2, b2y2) - fminf(b1y1, b2y1);
        const float c2 = cw * cw + chh * chh + eps;
        const float dx = b2x1 + b2x2 - b1x1 - b1x2;
        const float dy = b2y1 + b2y2 - b1y1 - b1y2;
        const float rho2 = (dx * dx + dy * dy) * 0.25f;
        const float dat = atanf(w2 / h2) - atanf(w1 / h1);
        const float v = 0.4052847345693511f * dat * dat;
        const float alpha = v / (1.0f + eps - iou0 + v);
        const float iou = iou0 - (rho2 / c2 + v * alpha);

        atomicAdd(&g_acc[li * 3 + 0], 1.0f - iou);
        atomicAdd(&g_acc[li * 3 + 1], 1.0f);
        atomicAdd(&g_acc[li * 3 + 2], lc);

        // telescoping winner correction: per-cell sum -> x * t_winner
        const float tval = fmaxf(iou, 0.0f);
        const unsigned long long packed =
            (((unsigned long long)(r + 1)) << 32) |
            (unsigned long long)__float_as_uint(tval);
        const unsigned long long old = atomicMax(&g_tobj[base + cell], packed);
        if (packed > old) {
            const float t_old = __uint_as_float((unsigned int)(old & 0xffffffffull));
            atomicAdd(&g_acc[9], -ps4 * (tval - t_old) * wly);
        }

        g_rcell[warp] = base + cell;
    }
}

// ---------------------------------------------------------------------------
// Kernel 2: blind-clear touched g_tobj cells + scalar epilogue (1 block).
// ---------------------------------------------------------------------------
__global__ __launch_bounds__(256)
void finalize_kernel(float* __restrict__ out, int out_size, int total_rows)
{
    // clear touched cells (idempotent blind stores, latency-hidden)
    for (int j = threadIdx.x; j < total_rows; j += 256) {
        const int cell = g_rcell[j];
        if (cell >= 0) g_tobj[cell] = 0ull;
    }

    if (threadIdx.x == 0) {
        float lbox = 0.0f, lcls = 0.0f;
        #pragma unroll
        for (int l = 0; l < 3; l++) {
            const float nv = fmaxf(g_acc[l * 3 + 1], 1.0f);
            lbox += g_acc[l * 3 + 0] / nv;
            lcls += g_acc[l * 3 + 2] / (nv * (float)NCLS);
        }
        const float lobj = g_acc[9];
        lbox *= 0.05f;
        lcls *= 0.5f;
        const float loss = lbox + lobj + lcls;

        if (out_size >= 5) {
            out[0] = loss;
            out[1] = lbox;
            out[2] = lobj;
            out[3] = lcls;
            out[4] = loss;
            for (int i = 5; i < out_size; i++) out[i] = 0.0f;
        } else if (out_size == 4) {
            out[0] = lbox; out[1] = lobj; out[2] = lcls; out[3] = loss;
        } else {
            for (int i = 0; i < out_size; i++) out[i] = loss;
        }

        #pragma unroll
        for (int i = 0; i < 10; i++) g_acc[i] = 0.0f;
    }
}

extern "C" void kernel_launch(void* const* d_in, const int* in_sizes, int n_in,
                              void* d_out, int out_size)
{
    const float* p0 = (const float*)d_in[0];
    const float* p1 = (const float*)d_in[1];
    const float* p2 = (const float*)d_in[2];
    const float* tg = (const float*)d_in[3];
    const float* an = (const float*)d_in[4];

    int nt = in_sizes[3] / 6;                        // 300
    int total_rows = 3 * NA * nt;                    // 2700
    int row_blocks = (total_rows * 32 + 255) / 256;  // 338

    main_kernel<<<STREAM_BLOCKS + row_blocks, 256>>>(p0, p1, p2, tg, an, nt);
    finalize_kernel<<<1, 256>>>((float*)d_out, out_size, total_rows);
}

// round 14
// speedup vs baseline: 1.4646x; 1.1026x over previous
#include <cuda_runtime.h>
#include <math.h>

// ---------------------------------------------------------------------------
// YOLO loss (3 layers, B=16, na=3, C=85, H/W = 80/40/20, nc=80)
//
// lobj = mean(softplus(x)) - mean(x * t_winner).  Sparse term built
// incrementally via telescoping atomicMax: when a row improves a cell's
// packed (priority, t) entry it adds x*(t_new - t_displaced); the per-cell
// sum converges to x*t_winner under ANY serialization order.
//
// Kernel 1: dense softplus stream (7 cells/thread, MLP=7) + row warps.
// Kernel 2: WIDE blind-clear of touched g_tobj cells (1 row/thread, 12
//           blocks -> one independent load+store per thread, no alias
//           serialization) + scalar epilogue in block 0.
//
// Scratch (__device__ globals, zero at load; invariant restored per replay):
//   g_tobj  : packed entries at matched cells only (cleared by kernel 2)
//   g_rcell : per-row touched cell index or -1 (rewritten every replay)
//   g_acc   : [l*3+0]=sum(1-iou) [l*3+1]=nvalid [l*3+2]=sum lcls (l=0..2)
//             [9] = lobj accumulator (softplus stream - x*t corrections)
// ---------------------------------------------------------------------------

#define B_IMG   16
#define NA      3
#define NCLS    80
#define CDIM    85

#define N0 307200
#define N1 76800
#define N2 19200
#define NTOT (N0 + N1 + N2)       // 403200
#define CELLS_PER_THREAD 7
#define STREAM_BLOCKS 225         // 403200 / (256 * 7)
#define MAX_ROWS 4096

__device__ unsigned long long g_tobj[NTOT];
__device__ int   g_rcell[MAX_ROWS];
__device__ float g_acc[10];

__device__ __forceinline__ float bce_logits(float x, float t) {
    return fmaxf(x, 0.0f) - x * t + log1pf(expf(-fabsf(x)));
}

// ---------------------------------------------------------------------------
// Kernel 1: dense stream + row warps
// ---------------------------------------------------------------------------
__global__ __launch_bounds__(256)
void main_kernel(const float* __restrict__ p0,
                 const float* __restrict__ p1,
                 const float* __restrict__ p2,
                 const float* __restrict__ targets,
                 const float* __restrict__ anchors,
                 int nt)
{
    const int rows_per_layer = NA * nt;
    const int total_rows = 3 * rows_per_layer;

    if (blockIdx.x < STREAM_BLOCKS) {
        // ---- dense objectness: 7 independent strided loads per thread ----
        const int g0 = blockIdx.x * (256 * CELLS_PER_THREAD) + threadIdx.x;
        float x[CELLS_PER_THREAD], wt[CELLS_PER_THREAD];
        #pragma unroll
        for (int i = 0; i < CELLS_PER_THREAD; i++) {
            const int g = g0 + i * 256;
            const float* ptr;
            if (g < N0)           { ptr = p0 + (size_t)g * CDIM + 4;              wt[i] = 1.0f / (float)N0; }
            else if (g < N0 + N1) { ptr = p1 + (size_t)(g - N0) * CDIM + 4;       wt[i] = 1.0f / (float)N1; }
            else                  { ptr = p2 + (size_t)(g - N0 - N1) * CDIM + 4;  wt[i] = 1.0f / (float)N2; }
            x[i] = __ldcs(ptr);
        }
        float acc = 0.0f;
        #pragma unroll
        for (int i = 0; i < CELLS_PER_THREAD; i++) {
            const float sp = fmaxf(x[i], 0.0f) +
                             __logf(1.0f + __expf(-fabsf(x[i])));
            acc += sp * wt[i];
        }
        __shared__ float s[8];
        const int lane = threadIdx.x & 31;
        const int wrp  = threadIdx.x >> 5;
        #pragma unroll
        for (int o = 16; o; o >>= 1)
            acc += __shfl_down_sync(0xffffffffu, acc, o);
        if (lane == 0) s[wrp] = acc;
        __syncthreads();
        if (threadIdx.x < 8) {
            float w = s[threadIdx.x];
            #pragma unroll
            for (int o = 4; o; o >>= 1)
                w += __shfl_down_sync(0x000000ffu, w, o);
            if (threadIdx.x == 0)
                atomicAdd(&g_acc[9], w);
        }
        return;
    }

    // ---- row path: one warp per (layer, anchor, target) ----
    const int warp = (blockIdx.x - STREAM_BLOCKS) * 8 + (threadIdx.x >> 5);
    const int lane = threadIdx.x & 31;
    if (warp >= total_rows) return;

    const int li = warp / rows_per_layer;
    const int r  = warp - li * rows_per_layer;    // a*nt + ti
    const int a  = r / nt;
    const int ti = r - a * nt;

    const int Wd = (li == 0) ? 80 : (li == 1) ? 40 : 20;
    const int Hd = Wd;
    const float* p = (li == 0) ? p0 : (li == 1) ? p1 : p2;
    const int base = (li == 0) ? 0 : (li == 1) ? N0 : (N0 + N1);
    const float wly = (li == 0) ? (1.0f / (float)N0)
                   : (li == 1) ? (1.0f / (float)N1) : (1.0f / (float)N2);

    const float timg = targets[ti * 6 + 0];
    const float tcls = targets[ti * 6 + 1];
    const float gx = targets[ti * 6 + 2] * (float)Wd;
    const float gy = targets[ti * 6 + 3] * (float)Hd;
    const float gw = targets[ti * 6 + 4] * (float)Wd;
    const float gh = targets[ti * 6 + 5] * (float)Hd;

    const float aw = anchors[(li * 3 + a) * 2 + 0];
    const float ah = anchors[(li * 3 + a) * 2 + 1];
    const float rw = gw / aw, rh = gh / ah;
    const float mr = fmaxf(fmaxf(rw, 1.0f / rw), fmaxf(rh, 1.0f / rh));
    if (!(mr < 4.0f)) {
        if (lane == 0) g_rcell[warp] = -1;
        return;
    }

    const int b = (int)timg;
    const int c = (int)tcls;
    const int gij_x = (int)gx;
    const int gij_y = (int)gy;
    const int gi = min(max(gij_x, 0), Wd - 1);
    const int gj = min(max(gij_y, 0), Hd - 1);
    const int match = B_IMG - 1 - b;

    const int cell = ((match * NA + a) * Hd + gj) * Wd + gi;
    const float* ps = p + (size_t)cell * CDIM;

    const float v0 = ps[lane];
    const float v1 = ps[lane + 32];
    const float v2 = (lane + 64 < CDIM) ? ps[lane + 64] : 0.0f;

    float lc = 0.0f;
    if (lane >= 5)
        lc += bce_logits(v0, (lane - 5) == c ? 1.0f : 0.0f);
    lc += bce_logits(v1, (lane + 32 - 5) == c ? 1.0f : 0.0f);
    if (lane + 64 < CDIM)
        lc += bce_logits(v2, (lane + 64 - 5) == c ? 1.0f : 0.0f);
    #pragma unroll
    for (int o = 16; o; o >>= 1)
        lc += __shfl_down_sync(0xffffffffu, lc, o);

    const float ps0 = __shfl_sync(0xffffffffu, v0, 0);
    const float ps1 = __shfl_sync(0xffffffffu, v0, 1);
    const float ps2 = __shfl_sync(0xffffffffu, v0, 2);
    const float ps3 = __shfl_sync(0xffffffffu, v0, 3);
    const float ps4 = __shfl_sync(0xffffffffu, v0, 4);

    if (lane == 0) {
        // reference quirk: anch = anchors[a, a]
        const float anw = anchors[(a * 3 + a) * 2 + 0];
        const float anh = anchors[(a * 3 + a) * 2 + 1];

        const float px = 1.0f / (1.0f + expf(-ps0));
        const float py = 1.0f / (1.0f + expf(-ps1));
        const float pw = expf(ps2) * anw;
        const float ph = expf(ps3) * anh;
        const float tx = gx - (float)gij_x;
        const float ty = gy - (float)gij_y;

        const float eps = 1e-9f;
        const float b1x1 = px - pw * 0.5f, b1x2 = px + pw * 0.5f;
        const float b1y1 = py - ph * 0.5f, b1y2 = py + ph * 0.5f;
        const float b2x1 = tx - gw * 0.5f, b2x2 = tx + gw * 0.5f;
        const float b2y1 = ty - gh * 0.5f, b2y2 = ty + gh * 0.5f;
        const float inter =
            fmaxf(fminf(b1x2, b2x2) - fmaxf(b1x1, b2x1), 0.0f) *
            fmaxf(fminf(b1y2, b2y2) - fmaxf(b1y1, b2y1), 0.0f);
        const float w1 = b1x2 - b1x1, h1 = b1y2 - b1y1 + eps;
        const float w2 = b2x2 - b2x1, h2 = b2y2 - b2y1 + eps;
        const float uni = w1 * h1 + w2 * h2 - inter + eps;
        const float iou0 = inter / uni;
        const float cw = fmaxf(b1x2, b2x2) - fminf(b1x1, b2x1);
        const float chh = fmaxf(b1y2, b2y2) - fminf(b1y1, b2y1);
        const float c2 = cw * cw + chh * chh + eps;
        const float dx = b2x1 + b2x2 - b1x1 - b1x2;
        const float dy = b2y1 + b2y2 - b1y1 - b1y2;
        const float rho2 = (dx * dx + dy * dy) * 0.25f;
        const float dat = atanf(w2 / h2) - atanf(w1 / h1);
        const float v = 0.4052847345693511f * dat * dat;
        const float alpha = v / (1.0f + eps - iou0 + v);
        const float iou = iou0 - (rho2 / c2 + v * alpha);

        atomicAdd(&g_acc[li * 3 + 0], 1.0f - iou);
        atomicAdd(&g_acc[li * 3 + 1], 1.0f);
        atomicAdd(&g_acc[li * 3 + 2], lc);

        // telescoping winner correction: per-cell sum -> x * t_winner
        const float tval = fmaxf(iou, 0.0f);
        const unsigned long long packed =
            (((unsigned long long)(r + 1)) << 32) |
            (unsigned long long)__float_as_uint(tval);
        const unsigned long long old = atomicMax(&g_tobj[base + cell], packed);
        if (packed > old) {
            const float t_old = __uint_as_float((unsigned int)(old & 0xffffffffull));
            atomicAdd(&g_acc[9], -ps4 * (tval - t_old) * wly);
        }

        g_rcell[warp] = base + cell;
    }
}

// ---------------------------------------------------------------------------
// Kernel 2: wide blind-clear (1 row/thread) + scalar epilogue (block 0).
// ---------------------------------------------------------------------------
__global__ __launch_bounds__(256)
void finalize_kernel(float* __restrict__ out, int out_size, int total_rows)
{
    const int j = blockIdx.x * 256 + threadIdx.x;
    if (j < total_rows) {
        const int cell = g_rcell[j];
        if (cell >= 0) g_tobj[cell] = 0ull;   // idempotent blind store
    }

    if (blockIdx.x == 0 && threadIdx.x == 0) {
        float lbox = 0.0f, lcls = 0.0f;
        #pragma unroll
        for (int l = 0; l < 3; l++) {
            const float nv = fmaxf(g_acc[l * 3 + 1], 1.0f);
            lbox += g_acc[l * 3 + 0] / nv;
            lcls += g_acc[l * 3 + 2] / (nv * (float)NCLS);
        }
        const float lobj = g_acc[9];
        lbox *= 0.05f;
        lcls *= 0.5f;
        const float loss = lbox + lobj + lcls;

        if (out_size >= 5) {
            out[0] = loss;
            out[1] = lbox;
            out[2] = lobj;
            out[3] = lcls;
            out[4] = loss;
            for (int i = 5; i < out_size; i++) out[i] = 0.0f;
        } else if (out_size == 4) {
            out[0] = lbox; out[1] = lobj; out[2] = lcls; out[3] = loss;
        } else {
            for (int i = 0; i < out_size; i++) out[i] = loss;
        }

        #pragma unroll
        for (int i = 0; i < 10; i++) g_acc[i] = 0.0f;
    }
}

extern "C" void kernel_launch(void* const* d_in, const int* in_sizes, int n_in,
                              void* d_out, int out_size)
{
    const float* p0 = (const float*)d_in[0];
    const float* p1 = (const float*)d_in[1];
    const float* p2 = (const float*)d_in[2];
    const float* tg = (const float*)d_in[3];
    const float* an = (const float*)d_in[4];

    int nt = in_sizes[3] / 6;                        // 300
    int total_rows = 3 * NA * nt;                    // 2700
    int row_blocks = (total_rows * 32 + 255) / 256;  // 338
    int fin_blocks = (total_rows + 255) / 256;       // 11

    main_kernel<<<STREAM_BLOCKS + row_blocks, 256>>>(p0, p1, p2, tg, an, nt);
    finalize_kernel<<<fin_blocks, 256>>>((float*)d_out, out_size, total_rows);
}